// round 9
// baseline (speedup 1.0000x reference)
#include <cuda_runtime.h>

// GCN 2-layer: N=50000 nodes, E=640000 edges, 128 -> 128(relu) -> 40
// Factorized normalization: y = dinv * (x @ W); agg[dst] += y[src] (+ self y[dst]);
// out = dinv * agg + b.

#define NN 50000
#define NE 640000

// Scratch (device globals — allocation is forbidden)
__device__ int   g_is32;          // 1 if edge_index delivered as int32, 0 if int64
__device__ int   g_src[NE];
__device__ int   g_dst[NE];
__device__ int   g_deg[NN];
__device__ float g_dinv[NN];
__device__ __align__(16) float g_y1[NN * 128];   // layer1 scaled GEMM out; reused as h
__device__ __align__(16) float g_agg1[NN * 128];
__device__ __align__(16) float g_y2[NN * 40];

// ---------------- edge-index dtype probe + conversion ----------------

__global__ void k_probe(const int* __restrict__ ei32) {
    // int64 view as int32: odd words are high halves == 0 (values < 50000).
    // genuine int32: odd words are random src indices, ~never all zero.
    int i = threadIdx.x;                 // 0..255, check odd words 1,3,...,511
    if (i == 0) g_is32 = 0;
    __syncthreads();
    if (ei32[2 * i + 1] != 0) g_is32 = 1;
}

__global__ void k_convert(const int* __restrict__ ei32, int ne, int nn) {
    int e = blockIdx.x * blockDim.x + threadIdx.x;
    if (e >= ne) return;
    int s, d;
    if (g_is32) {
        s = ei32[e];
        d = ei32[ne + e];
    } else {                              // int64 little-endian: take low words
        s = ei32[2 * e];
        d = ei32[2 * ne + 2 * e];
    }
    // safety clamp (wrong answer beats illegal access for diagnosis)
    g_src[e] = ((unsigned)s < (unsigned)nn) ? s : 0;
    g_dst[e] = ((unsigned)d < (unsigned)nn) ? d : 0;
}

// ---------------- degree / normalization ----------------

__global__ void k_zero_deg(int nn) {
    int i = blockIdx.x * blockDim.x + threadIdx.x;
    if (i < nn) g_deg[i] = 0;
}

__global__ void k_count(int ne) {
    int e = blockIdx.x * blockDim.x + threadIdx.x;
    if (e < ne) atomicAdd(&g_deg[g_dst[e]], 1);
}

__global__ void k_dinv(int nn) {
    int i = blockIdx.x * blockDim.x + threadIdx.x;
    if (i < nn) g_dinv[i] = rsqrtf((float)(g_deg[i] + 1));  // +1 self loop; > 0 always
}

// ---------------- layer 1: y1 = dinv * (x @ W1) ----------------
// 8 rows per block, 128 threads (one output column each).

__global__ void k_gemm1(const float* __restrict__ x, const float* __restrict__ W1, int nn) {
    __shared__ float xs[8][128];
    int row0 = blockIdx.x * 8;
    int c = threadIdx.x;
#pragma unroll
    for (int r = 0; r < 8; r++) {
        int row = row0 + r;
        xs[r][c] = (row < nn) ? x[row * 128 + c] : 0.f;
    }
    __syncthreads();
    float acc[8];
#pragma unroll
    for (int r = 0; r < 8; r++) acc[r] = 0.f;
    for (int k = 0; k < 128; k++) {
        float w = W1[k * 128 + c];
#pragma unroll
        for (int r = 0; r < 8; r++) acc[r] = fmaf(xs[r][k], w, acc[r]);
    }
#pragma unroll
    for (int r = 0; r < 8; r++) {
        int row = row0 + r;
        if (row < nn) g_y1[row * 128 + c] = acc[r] * g_dinv[row];
    }
}

// agg1 = y1  (self-loop init)
__global__ void k_copy128(int nn) {
    int i = blockIdx.x * blockDim.x + threadIdx.x;
    if (i < nn * 32) ((float4*)g_agg1)[i] = ((const float4*)g_y1)[i];
}

// one warp per edge: 32 lanes x float4 = 128 channels
__global__ void k_scatter1(int ne) {
    int idx = blockIdx.x * blockDim.x + threadIdx.x;
    int e = idx >> 5;
    if (e >= ne) return;
    int q = idx & 31;
    int s = g_src[e];
    int d = g_dst[e];
    float4 v = ((const float4*)(g_y1 + (size_t)s * 128))[q];
    float* a = g_agg1 + (size_t)d * 128 + q * 4;
    atomicAdd(a + 0, v.x);
    atomicAdd(a + 1, v.y);
    atomicAdd(a + 2, v.z);
    atomicAdd(a + 3, v.w);
}

// h = relu(dinv * agg1 + b1), written back over g_y1
__global__ void k_finish1(const float* __restrict__ b1, int nn) {
    int i = blockIdx.x * blockDim.x + threadIdx.x;
    if (i < nn * 128) {
        int row = i >> 7, c = i & 127;
        g_y1[i] = fmaxf(fmaf(g_dinv[row], g_agg1[i], b1[c]), 0.f);
    }
}

// ---------------- layer 2: y2 = dinv * (h @ W2) ----------------
// 6 rows per block, 240 threads: thread t -> (col = t%40, row = t/40)

__global__ void k_gemm2(const float* __restrict__ W2, int nn) {
    __shared__ float hs[6][129];
    int row0 = blockIdx.x * 6;
    int t = threadIdx.x;
    for (int i = t; i < 6 * 128; i += 240) {
        int r = i >> 7, k = i & 127;
        int row = row0 + r;
        hs[r][k] = (row < nn) ? g_y1[row * 128 + k] : 0.f;
    }
    __syncthreads();
    int c = t % 40, r = t / 40;
    int row = row0 + r;
    if (row < nn) {
        float acc = 0.f;
#pragma unroll 4
        for (int k = 0; k < 128; k++) acc = fmaf(hs[r][k], W2[k * 40 + c], acc);
        g_y2[row * 40 + c] = acc * g_dinv[row];
    }
}

// out = y2  (self-loop init, directly into d_out)
__global__ void k_copy40(float* __restrict__ out, int nn) {
    int i = blockIdx.x * blockDim.x + threadIdx.x;
    if (i < nn * 10) ((float4*)out)[i] = ((const float4*)g_y2)[i];
}

// 10 float4 per edge (40 channels)
__global__ void k_scatter2(float* __restrict__ out, int ne) {
    int idx = blockIdx.x * blockDim.x + threadIdx.x;
    int e = idx / 10;
    if (e >= ne) return;
    int q = idx - e * 10;
    int s = g_src[e];
    int d = g_dst[e];
    float4 v = *(const float4*)(g_y2 + (size_t)s * 40 + q * 4);
    float* a = out + (size_t)d * 40 + q * 4;
    atomicAdd(a + 0, v.x);
    atomicAdd(a + 1, v.y);
    atomicAdd(a + 2, v.z);
    atomicAdd(a + 3, v.w);
}

// out = dinv * out + b2  (in place)
__global__ void k_final(float* __restrict__ out, const float* __restrict__ b2, int nn) {
    int i = blockIdx.x * blockDim.x + threadIdx.x;
    if (i < nn * 40) {
        int row = i / 40, c = i - row * 40;
        out[i] = fmaf(g_dinv[row], out[i], b2[c]);
    }
}

extern "C" void kernel_launch(void* const* d_in, const int* in_sizes, int n_in,
                              void* d_out, int out_size) {
    const float* x    = (const float*)d_in[0];
    const int*   ei32 = (const int*)d_in[1];   // int32 view; int64 handled via probe
    const float* W1   = (const float*)d_in[2];
    const float* b1   = (const float*)d_in[3];
    const float* W2   = (const float*)d_in[4];
    const float* b2   = (const float*)d_in[5];
    float*       out  = (float*)d_out;

    const int nn = in_sizes[0] / 128;           // 50000
    const int ne = in_sizes[1] / 2;             // 640000 (element count same for i32/i64)

    k_probe<<<1, 256>>>(ei32);
    k_convert<<<(ne + 255) / 256, 256>>>(ei32, ne, nn);

    k_zero_deg<<<(nn + 255) / 256, 256>>>(nn);
    k_count<<<(ne + 255) / 256, 256>>>(ne);
    k_dinv<<<(nn + 255) / 256, 256>>>(nn);

    // layer 1
    k_gemm1<<<(nn + 7) / 8, 128>>>(x, W1, nn);
    k_copy128<<<(nn * 32 + 255) / 256, 256>>>(nn);
    k_scatter1<<<(int)(((long long)ne * 32 + 255) / 256), 256>>>(ne);
    k_finish1<<<(nn * 128 + 255) / 256, 256>>>(b1, nn);

    // layer 2
    k_gemm2<<<(nn + 5) / 6, 240>>>(W2, nn);
    k_copy40<<<(nn * 10 + 255) / 256, 256>>>(out, nn);
    k_scatter2<<<(int)(((long long)ne * 10 + 255) / 256), 256>>>(out, ne);
    k_final<<<(nn * 40 + 255) / 256, 256>>>(out, b2, nn);
}

// round 10
// speedup vs baseline: 1.9207x; 1.9207x over previous
#include <cuda_runtime.h>

// GCN 2-layer, N=50000, E=640000, 128 -> 128(relu) -> 40.
// Factorized norm: y = dinv*(x@W); agg[d] = y[d] + sum_{e:dst=d} y[src_e]; out = dinv*agg + b.
// Aggregation via by-destination CSR + per-node warp gather (no feature atomics).

#define NN 50000
#define NE 640000

// ---- scratch (device globals; allocation forbidden) ----
__device__ int   g_is32;
__device__ int   g_src[NE];
__device__ int   g_dst[NE];
__device__ int   g_eidx[NE];        // CSR column indices (src), grouped by dst
__device__ int   g_rowptr[NN + 1];
__device__ int   g_cursor[NN];
__device__ int   g_rowtmp[NN];
__device__ int   g_bsum[256];
__device__ int   g_boff[256];
__device__ int   g_deg[NN];
__device__ float g_dinv[NN];
__device__ __align__(16) float g_y1[NN * 128];
__device__ __align__(16) float g_h [NN * 128];
__device__ __align__(16) float g_y2[NN * 40];

// ---------------- edge-index dtype probe ----------------
__global__ void k_probe(const int* __restrict__ ei32) {
    int i = threadIdx.x;                       // check odd 32-bit words 1..511
    if (i == 0) g_is32 = 0;
    __syncthreads();
    if (ei32[2 * i + 1] != 0) g_is32 = 1;      // int64 high halves are all 0
}

__global__ void k_zero_deg(int nn) {
    int i = blockIdx.x * blockDim.x + threadIdx.x;
    if (i < nn) g_deg[i] = 0;
}

// convert to int32 src/dst + count in-degree (fused)
__global__ void k_convert_count(const int* __restrict__ ei32, int ne, int nn) {
    int e = blockIdx.x * blockDim.x + threadIdx.x;
    if (e >= ne) return;
    int s, d;
    if (g_is32) { s = ei32[e];     d = ei32[ne + e]; }
    else        { s = ei32[2 * e]; d = ei32[2 * ne + 2 * e]; }
    s = ((unsigned)s < (unsigned)nn) ? s : 0;   // safety clamp
    d = ((unsigned)d < (unsigned)nn) ? d : 0;
    g_src[e] = s;
    g_dst[e] = d;
    atomicAdd(&g_deg[d], 1);
}

// ---------------- exclusive scan of deg -> rowptr ----------------
__global__ void k_scan1(int nn) {
    __shared__ int s[256];
    int t = threadIdx.x;
    int i = blockIdx.x * 256 + t;
    int v = (i < nn) ? g_deg[i] : 0;
    s[t] = v;
    __syncthreads();
    for (int off = 1; off < 256; off <<= 1) {
        int add = (t >= off) ? s[t - off] : 0;
        __syncthreads();
        s[t] += add;
        __syncthreads();
    }
    if (i < nn) g_rowtmp[i] = s[t] - v;         // exclusive
    if (t == 255) g_bsum[blockIdx.x] = s[255];
}

__global__ void k_scan2(int nb) {
    __shared__ int s[256];
    int t = threadIdx.x;
    int v = (t < nb) ? g_bsum[t] : 0;
    s[t] = v;
    __syncthreads();
    for (int off = 1; off < 256; off <<= 1) {
        int add = (t >= off) ? s[t - off] : 0;
        __syncthreads();
        s[t] += add;
        __syncthreads();
    }
    g_boff[t] = s[t] - v;
}

__global__ void k_scan3(int nn, int ne) {
    int i = blockIdx.x * blockDim.x + threadIdx.x;
    if (i < nn) {
        int rp = g_rowtmp[i] + g_boff[i >> 8];
        g_rowptr[i] = rp;
        g_cursor[i] = rp;
        g_dinv[i] = rsqrtf((float)(g_deg[i] + 1));   // +1 self loop
    }
    if (i == 0) g_rowptr[nn] = ne;
}

__global__ void k_fill(int ne) {
    int e = blockIdx.x * blockDim.x + threadIdx.x;
    if (e >= ne) return;
    int pos = atomicAdd(&g_cursor[g_dst[e]], 1);
    g_eidx[pos] = g_src[e];
}

// ---------------- layer 1 GEMM: y1 = dinv * (x @ W1) ----------------
// 256 threads, 32 rows/block; thread = (lane -> 4 cols, warp -> 4 rows). 16 FFMA / 5 loads.
__global__ void k_gemm1(const float* __restrict__ x, const float* __restrict__ W1, int nn) {
    __shared__ float xs[32][128];
    int row0 = blockIdx.x * 32;
    int tid = threadIdx.x;
    for (int i = tid; i < 32 * 32; i += 256) {   // 1024 float4 loads
        int r = i >> 5, cq = i & 31;
        int row = row0 + r;
        float4 v = make_float4(0.f, 0.f, 0.f, 0.f);
        if (row < nn) v = ((const float4*)(x + (size_t)row * 128))[cq];
        ((float4*)&xs[r][0])[cq] = v;
    }
    __syncthreads();
    int lane = tid & 31;       // 4 output cols: lane*4..lane*4+3
    int rg = tid >> 5;         // 4 rows: rg*4..rg*4+3
    float4 a0 = make_float4(0.f, 0.f, 0.f, 0.f), a1 = a0, a2 = a0, a3 = a0;
    const float4* W4 = (const float4*)W1;
#pragma unroll 4
    for (int k = 0; k < 128; k++) {
        float4 w = W4[k * 32 + lane];
        float x0 = xs[rg * 4 + 0][k];
        float x1 = xs[rg * 4 + 1][k];
        float x2 = xs[rg * 4 + 2][k];
        float x3 = xs[rg * 4 + 3][k];
        a0.x = fmaf(x0, w.x, a0.x); a0.y = fmaf(x0, w.y, a0.y); a0.z = fmaf(x0, w.z, a0.z); a0.w = fmaf(x0, w.w, a0.w);
        a1.x = fmaf(x1, w.x, a1.x); a1.y = fmaf(x1, w.y, a1.y); a1.z = fmaf(x1, w.z, a1.z); a1.w = fmaf(x1, w.w, a1.w);
        a2.x = fmaf(x2, w.x, a2.x); a2.y = fmaf(x2, w.y, a2.y); a2.z = fmaf(x2, w.z, a2.z); a2.w = fmaf(x2, w.w, a2.w);
        a3.x = fmaf(x3, w.x, a3.x); a3.y = fmaf(x3, w.y, a3.y); a3.z = fmaf(x3, w.z, a3.z); a3.w = fmaf(x3, w.w, a3.w);
    }
    float4 accs[4] = {a0, a1, a2, a3};
#pragma unroll
    for (int j = 0; j < 4; j++) {
        int row = row0 + rg * 4 + j;
        if (row < nn) {
            float di = g_dinv[row];
            float4 v = accs[j];
            v.x *= di; v.y *= di; v.z *= di; v.w *= di;
            ((float4*)(g_y1 + (size_t)row * 128))[lane] = v;
        }
    }
}

// ---------------- layer 1 gather: h = relu(dinv*(y1[d] + sum y1[src]) + b1) ----------------
// one warp per node; lane q owns float4 chunk q (32 * 16B = 512B row).
__global__ void k_gather1(const float* __restrict__ b1, int nn) {
    int warp = (blockIdx.x * blockDim.x + threadIdx.x) >> 5;
    if (warp >= nn) return;
    int q = threadIdx.x & 31;
    int n = warp;
    int beg = g_rowptr[n], end = g_rowptr[n + 1];
    float4 acc = ((const float4*)(g_y1 + (size_t)n * 128))[q];   // self loop
    int k = beg;
    for (; k + 1 < end; k += 2) {                                // 2 loads in flight
        int s0 = g_eidx[k], s1 = g_eidx[k + 1];
        float4 v0 = ((const float4*)(g_y1 + (size_t)s0 * 128))[q];
        float4 v1 = ((const float4*)(g_y1 + (size_t)s1 * 128))[q];
        acc.x += v0.x; acc.y += v0.y; acc.z += v0.z; acc.w += v0.w;
        acc.x += v1.x; acc.y += v1.y; acc.z += v1.z; acc.w += v1.w;
    }
    if (k < end) {
        int s = g_eidx[k];
        float4 v = ((const float4*)(g_y1 + (size_t)s * 128))[q];
        acc.x += v.x; acc.y += v.y; acc.z += v.z; acc.w += v.w;
    }
    float di = g_dinv[n];
    float4 b = ((const float4*)b1)[q];
    float4 h;
    h.x = fmaxf(fmaf(di, acc.x, b.x), 0.f);
    h.y = fmaxf(fmaf(di, acc.y, b.y), 0.f);
    h.z = fmaxf(fmaf(di, acc.z, b.z), 0.f);
    h.w = fmaxf(fmaf(di, acc.w, b.w), 0.f);
    ((float4*)(g_h + (size_t)n * 128))[q] = h;
}

// ---------------- layer 2 GEMM: y2 = dinv * (h @ W2) ----------------
__global__ void k_gemm2(const float* __restrict__ W2, int nn) {
    __shared__ float hs[6][129];
    int row0 = blockIdx.x * 6;
    int t = threadIdx.x;   // 240
    for (int i = t; i < 6 * 128; i += 240) {
        int r = i >> 7, k = i & 127;
        int row = row0 + r;
        hs[r][k] = (row < nn) ? g_h[(size_t)row * 128 + k] : 0.f;
    }
    __syncthreads();
    int c = t % 40, r = t / 40;
    int row = row0 + r;
    if (row < nn) {
        float acc = 0.f;
#pragma unroll 4
        for (int k = 0; k < 128; k++) acc = fmaf(hs[r][k], W2[k * 40 + c], acc);
        g_y2[(size_t)row * 40 + c] = acc * g_dinv[row];
    }
}

// ---------------- layer 2 gather: out = dinv*(y2[d] + sum y2[src]) + b2 ----------------
// one warp per node; 3 sub-groups of 10 lanes each process every 3rd edge; shfl-reduce.
__global__ void k_gather2(float* __restrict__ out, const float* __restrict__ b2, int nn) {
    int warp = (blockIdx.x * blockDim.x + threadIdx.x) >> 5;
    if (warp >= nn) return;
    int lane = threadIdx.x & 31;
    int n = warp;
    int beg = g_rowptr[n], end = g_rowptr[n + 1];
    int sub = lane / 10;                 // 0,1,2 active; 3 -> idle lanes 30,31
    int q = lane % 10;                   // float4 chunk (40 ch = 10 float4)
    float4 acc = make_float4(0.f, 0.f, 0.f, 0.f);
    if (sub == 0) acc = ((const float4*)(g_y2 + (size_t)n * 40))[q];   // self loop
    int k = (sub < 3) ? (beg + sub) : end;
    for (; k < end; k += 3) {
        int s = g_eidx[k];
        float4 v = ((const float4*)(g_y2 + (size_t)s * 40))[q];
        acc.x += v.x; acc.y += v.y; acc.z += v.z; acc.w += v.w;
    }
    unsigned m = 0xFFFFFFFFu;
    float ax = acc.x + __shfl_sync(m, acc.x, lane + 10) + __shfl_sync(m, acc.x, lane + 20);
    float ay = acc.y + __shfl_sync(m, acc.y, lane + 10) + __shfl_sync(m, acc.y, lane + 20);
    float az = acc.z + __shfl_sync(m, acc.z, lane + 10) + __shfl_sync(m, acc.z, lane + 20);
    float aw = acc.w + __shfl_sync(m, acc.w, lane + 10) + __shfl_sync(m, acc.w, lane + 20);
    if (lane < 10) {
        float di = g_dinv[n];
        float4 b = ((const float4*)b2)[q];
        float4 r;
        r.x = fmaf(di, ax, b.x);
        r.y = fmaf(di, ay, b.y);
        r.z = fmaf(di, az, b.z);
        r.w = fmaf(di, aw, b.w);
        ((float4*)(out + (size_t)n * 40))[q] = r;
    }
}

extern "C" void kernel_launch(void* const* d_in, const int* in_sizes, int n_in,
                              void* d_out, int out_size) {
    const float* x    = (const float*)d_in[0];
    const int*   ei32 = (const int*)d_in[1];
    const float* W1   = (const float*)d_in[2];
    const float* b1   = (const float*)d_in[3];
    const float* W2   = (const float*)d_in[4];
    const float* b2   = (const float*)d_in[5];
    float*       out  = (float*)d_out;

    const int nn = in_sizes[0] / 128;     // 50000
    const int ne = in_sizes[1] / 2;       // 640000
    const int nb = (nn + 255) / 256;      // scan blocks (196 <= 256)

    k_probe<<<1, 256>>>(ei32);
    k_zero_deg<<<nb, 256>>>(nn);
    k_convert_count<<<(ne + 255) / 256, 256>>>(ei32, ne, nn);

    k_scan1<<<nb, 256>>>(nn);
    k_scan2<<<1, 256>>>(nb);
    k_scan3<<<nb, 256>>>(nn, ne);
    k_fill<<<(ne + 255) / 256, 256>>>(ne);

    // layer 1
    k_gemm1<<<(nn + 31) / 32, 256>>>(x, W1, nn);
    k_gather1<<<(nn + 7) / 8, 256>>>(b1, nn);     // 8 warps/block, warp per node

    // layer 2
    k_gemm2<<<(nn + 5) / 6, 240>>>(W2, nn);
    k_gather2<<<(nn + 7) / 8, 256>>>(out, b2, nn);
}

// round 11
// speedup vs baseline: 2.9714x; 1.5470x over previous
#include <cuda_runtime.h>
#include <cuda_bf16.h>
#include <stdint.h>

// GCN 2-layer, N=50000, E=640000, 128 -> 128(relu) -> 40.
// y = dinv*(x@W) via bf16x3 tensor-core GEMM; agg via CSR warp-gather; out = dinv*agg + b.

#define NN 50000
#define NE 640000

// ---- scratch (device globals; allocation forbidden) ----
__device__ int   g_is32;
__device__ int   g_eidx[NE];
__device__ int   g_rowptr[NN + 1];
__device__ int   g_cursor[NN];
__device__ int   g_rowtmp[NN];
__device__ int   g_bsum[256];
__device__ int   g_boff[256];
__device__ int   g_deg[NN];
__device__ float g_dinv[NN];
__device__ __align__(16) float g_y1[NN * 128];
__device__ __align__(16) float g_h [NN * 128];
__device__ __align__(16) float g_y2[NN * 40];
__device__ __align__(4) __nv_bfloat16 g_W1h[128 * 128], g_W1l[128 * 128];
__device__ __align__(4) __nv_bfloat16 g_W2h[128 * 40],  g_W2l[128 * 40];

// ---------------- prologue ----------------
__global__ void k_probe(const int* __restrict__ ei32) {
    int i = threadIdx.x;                      // odd 32-bit words 1..511
    if (i == 0) g_is32 = 0;
    __syncthreads();
    if (ei32[2 * i + 1] != 0) g_is32 = 1;     // int64 high halves all 0
}

__global__ void k_zero_deg(int nn) {
    int i = blockIdx.x * blockDim.x + threadIdx.x;
    if (i < nn) g_deg[i] = 0;
}

__global__ void k_count(const int* __restrict__ ei32, int ne, int nn) {
    int e = blockIdx.x * blockDim.x + threadIdx.x;
    if (e >= ne) return;
    int d = g_is32 ? ei32[ne + e] : ei32[2 * ne + 2 * e];
    d = ((unsigned)d < (unsigned)nn) ? d : 0;
    atomicAdd(&g_deg[d], 1);
}

__global__ void k_scan1(int nn) {
    __shared__ int s[256];
    int t = threadIdx.x;
    int i = blockIdx.x * 256 + t;
    int v = (i < nn) ? g_deg[i] : 0;
    s[t] = v;
    __syncthreads();
    for (int off = 1; off < 256; off <<= 1) {
        int add = (t >= off) ? s[t - off] : 0;
        __syncthreads();
        s[t] += add;
        __syncthreads();
    }
    if (i < nn) g_rowtmp[i] = s[t] - v;
    if (t == 255) g_bsum[blockIdx.x] = s[255];
}

__global__ void k_scan2(int nb) {
    __shared__ int s[256];
    int t = threadIdx.x;
    int v = (t < nb) ? g_bsum[t] : 0;
    s[t] = v;
    __syncthreads();
    for (int off = 1; off < 256; off <<= 1) {
        int add = (t >= off) ? s[t - off] : 0;
        __syncthreads();
        s[t] += add;
        __syncthreads();
    }
    g_boff[t] = s[t] - v;
}

__global__ void k_scan3(int nn, int ne) {
    int i = blockIdx.x * blockDim.x + threadIdx.x;
    if (i < nn) {
        int rp = g_rowtmp[i] + g_boff[i >> 8];
        g_rowptr[i] = rp;
        g_cursor[i] = rp;
        g_dinv[i] = rsqrtf((float)(g_deg[i] + 1));
    }
    if (i == 0) g_rowptr[nn] = ne;
}

__global__ void k_fill(const int* __restrict__ ei32, int ne, int nn) {
    int e = blockIdx.x * blockDim.x + threadIdx.x;
    if (e >= ne) return;
    int s, d;
    if (g_is32) { s = ei32[e];     d = ei32[ne + e]; }
    else        { s = ei32[2 * e]; d = ei32[2 * ne + 2 * e]; }
    s = ((unsigned)s < (unsigned)nn) ? s : 0;
    d = ((unsigned)d < (unsigned)nn) ? d : 0;
    int pos = atomicAdd(&g_cursor[d], 1);
    g_eidx[pos] = s;
}

// ---------------- weight split: W -> bf16 hi + bf16 lo ----------------
__global__ void k_splitW(const float* __restrict__ W1, const float* __restrict__ W2) {
    int i = blockIdx.x * blockDim.x + threadIdx.x;
    if (i < 128 * 128) {
        float v = W1[i];
        __nv_bfloat16 h = __float2bfloat16(v);
        g_W1h[i] = h;
        g_W1l[i] = __float2bfloat16(v - __bfloat162float(h));
    } else if (i < 128 * 128 + 128 * 40) {
        int j = i - 128 * 128;
        float v = W2[j];
        __nv_bfloat16 h = __float2bfloat16(v);
        g_W2h[j] = h;
        g_W2l[j] = __float2bfloat16(v - __bfloat162float(h));
    }
}

// ---------------- tensor-core GEMM (bf16x3) ----------------
__device__ __forceinline__ uint32_t s2u(const void* p) {
    return (uint32_t)__cvta_generic_to_shared(p);
}
__device__ __forceinline__ uint32_t pack2(float a, float b) {
    __nv_bfloat162 t = __floats2bfloat162_rn(a, b);
    return *(uint32_t*)&t;
}
__device__ __forceinline__ void ldsm_x4(uint32_t a[4], uint32_t addr) {
    asm volatile("ldmatrix.sync.aligned.m8n8.x4.shared.b16 {%0,%1,%2,%3},[%4];"
                 : "=r"(a[0]), "=r"(a[1]), "=r"(a[2]), "=r"(a[3]) : "r"(addr));
}
__device__ __forceinline__ void ldsm_x2t(uint32_t b[2], uint32_t addr) {
    asm volatile("ldmatrix.sync.aligned.m8n8.x2.trans.shared.b16 {%0,%1},[%2];"
                 : "=r"(b[0]), "=r"(b[1]) : "r"(addr));
}
__device__ __forceinline__ void mma16816(float d[4], const uint32_t a[4], const uint32_t b[2]) {
    asm volatile("mma.sync.aligned.m16n8k16.row.col.f32.bf16.bf16.f32 "
                 "{%0,%1,%2,%3},{%4,%5,%6,%7},{%8,%9},{%0,%1,%2,%3};"
                 : "+f"(d[0]), "+f"(d[1]), "+f"(d[2]), "+f"(d[3])
                 : "r"(a[0]), "r"(a[1]), "r"(a[2]), "r"(a[3]), "r"(b[0]), "r"(b[1]));
}

// LAYER 1: in = x (arg), W = g_W1h/l, out = g_y1, NW=128
// LAYER 2: in = g_h,     W = g_W2h/l, out = g_y2, NW=40
// Block: 256 threads (8 warps x m16), M-tile 128, full N.
template <int LAYER>
__global__ void k_gemm_tc(const float* __restrict__ xin, int nn) {
    constexpr int NW = (LAYER == 1) ? 128 : 40;
    constexpr int NT = NW / 8;                  // n-tiles
    constexpr int XP = 136;                     // padded x width (bf16)
    constexpr int WP = (LAYER == 1) ? 136 : 56; // padded w width (bank-safe)

    extern __shared__ __nv_bfloat16 sm[];
    __nv_bfloat16* xh = sm;
    __nv_bfloat16* xl = xh + 128 * XP;
    __nv_bfloat16* wh = xl + 128 * XP;
    __nv_bfloat16* wl = wh + 128 * WP;

    const float* in = (LAYER == 1) ? xin : (const float*)g_h;
    float* outp     = (LAYER == 1) ? g_y1 : g_y2;
    const __nv_bfloat16* Wh = (LAYER == 1) ? g_W1h : g_W2h;
    const __nv_bfloat16* Wl = (LAYER == 1) ? g_W1l : g_W2l;

    int tid = threadIdx.x;
    int m_base = blockIdx.x * 128;

    // load W (bf16 pre-split) into padded smem, pairwise
    const uint32_t* wsh = (const uint32_t*)Wh;
    const uint32_t* wsl = (const uint32_t*)Wl;
    for (int i = tid; i < 128 * NW / 2; i += 256) {
        int r = (2 * i) / NW, c = (2 * i) % NW;
        *(uint32_t*)&wh[r * WP + c] = wsh[i];
        *(uint32_t*)&wl[r * WP + c] = wsl[i];
    }
    // load + split x tile (128 x 128 fp32)
    for (int i = tid; i < 128 * 32; i += 256) {
        int r = i >> 5, cq = i & 31;
        int row = m_base + r;
        float4 v = make_float4(0.f, 0.f, 0.f, 0.f);
        if (row < nn) v = ((const float4*)(in + (size_t)row * 128))[cq];
        float hx = __bfloat162float(__float2bfloat16(v.x));
        float hy = __bfloat162float(__float2bfloat16(v.y));
        float hz = __bfloat162float(__float2bfloat16(v.z));
        float hw = __bfloat162float(__float2bfloat16(v.w));
        uint2 ph = make_uint2(pack2(v.x, v.y), pack2(v.z, v.w));
        uint2 pl = make_uint2(pack2(v.x - hx, v.y - hy), pack2(v.z - hz, v.w - hw));
        *(uint2*)&xh[r * XP + cq * 4] = ph;
        *(uint2*)&xl[r * XP + cq * 4] = pl;
    }
    __syncthreads();

    int warp = tid >> 5, lane = tid & 31;
    int mrow = warp * 16;

    float d[NT][4];
#pragma unroll
    for (int t = 0; t < NT; t++) { d[t][0] = d[t][1] = d[t][2] = d[t][3] = 0.f; }

    uint32_t xh_b = s2u(xh), xl_b = s2u(xl), wh_b = s2u(wh), wl_b = s2u(wl);
    uint32_t a_off = ((mrow + (lane & 15)) * XP + (lane >> 4) * 8) * 2;   // bytes
    uint32_t b_lrow = (lane & 15);

#pragma unroll
    for (int ks = 0; ks < 8; ks++) {
        uint32_t ah[4], al[4];
        ldsm_x4(ah, xh_b + a_off + ks * 32);
        ldsm_x4(al, xl_b + a_off + ks * 32);
        uint32_t brow = ((ks * 16 + b_lrow) * WP) * 2;
#pragma unroll
        for (int nt = 0; nt < NT; nt++) {
            uint32_t bh[2], bl[2];
            ldsm_x2t(bh, wh_b + brow + nt * 16);
            ldsm_x2t(bl, wl_b + brow + nt * 16);
            mma16816(d[nt], ah, bh);
            mma16816(d[nt], ah, bl);
            mma16816(d[nt], al, bh);
        }
    }

    int r0 = m_base + mrow + (lane >> 2);
    int r1 = r0 + 8;
    int c0 = (lane & 3) * 2;
    float di0 = (r0 < nn) ? g_dinv[r0] : 0.f;
    float di1 = (r1 < nn) ? g_dinv[r1] : 0.f;
#pragma unroll
    for (int nt = 0; nt < NT; nt++) {
        int col = nt * 8 + c0;
        if (r0 < nn) *(float2*)&outp[(size_t)r0 * NW + col] = make_float2(d[nt][0] * di0, d[nt][1] * di0);
        if (r1 < nn) *(float2*)&outp[(size_t)r1 * NW + col] = make_float2(d[nt][2] * di1, d[nt][3] * di1);
    }
}

// ---------------- layer 1 gather: h = relu(dinv*(y1[n] + sum y1[src]) + b1) ----------------
__global__ void k_gather1(const float* __restrict__ b1, int nn) {
    int warp = (blockIdx.x * blockDim.x + threadIdx.x) >> 5;
    if (warp >= nn) return;
    int q = threadIdx.x & 31;
    int n = warp;
    int beg = g_rowptr[n], end = g_rowptr[n + 1];
    float4 acc = ((const float4*)(g_y1 + (size_t)n * 128))[q];   // self loop
    int k = beg;
    for (; k + 3 < end; k += 4) {                                // 4 loads in flight
        int s0 = g_eidx[k], s1 = g_eidx[k + 1], s2 = g_eidx[k + 2], s3 = g_eidx[k + 3];
        float4 v0 = ((const float4*)(g_y1 + (size_t)s0 * 128))[q];
        float4 v1 = ((const float4*)(g_y1 + (size_t)s1 * 128))[q];
        float4 v2 = ((const float4*)(g_y1 + (size_t)s2 * 128))[q];
        float4 v3 = ((const float4*)(g_y1 + (size_t)s3 * 128))[q];
        acc.x += v0.x + v1.x + v2.x + v3.x;
        acc.y += v0.y + v1.y + v2.y + v3.y;
        acc.z += v0.z + v1.z + v2.z + v3.z;
        acc.w += v0.w + v1.w + v2.w + v3.w;
    }
    for (; k < end; k++) {
        int s = g_eidx[k];
        float4 v = ((const float4*)(g_y1 + (size_t)s * 128))[q];
        acc.x += v.x; acc.y += v.y; acc.z += v.z; acc.w += v.w;
    }
    float di = g_dinv[n];
    float4 b = ((const float4*)b1)[q];
    float4 h;
    h.x = fmaxf(fmaf(di, acc.x, b.x), 0.f);
    h.y = fmaxf(fmaf(di, acc.y, b.y), 0.f);
    h.z = fmaxf(fmaf(di, acc.z, b.z), 0.f);
    h.w = fmaxf(fmaf(di, acc.w, b.w), 0.f);
    ((float4*)(g_h + (size_t)n * 128))[q] = h;
}

// ---------------- layer 2 gather: out = dinv*(y2[n] + sum y2[src]) + b2 ----------------
__global__ void k_gather2(float* __restrict__ out, const float* __restrict__ b2, int nn) {
    int warp = (blockIdx.x * blockDim.x + threadIdx.x) >> 5;
    if (warp >= nn) return;
    int lane = threadIdx.x & 31;
    int n = warp;
    int beg = g_rowptr[n], end = g_rowptr[n + 1];
    int sub = lane / 10;                 // 0,1,2 active
    int q = lane % 10;
    float4 acc = make_float4(0.f, 0.f, 0.f, 0.f);
    if (sub == 0) acc = ((const float4*)(g_y2 + (size_t)n * 40))[q];   // self loop
    int k = (sub < 3) ? (beg + sub) : end;
    for (; k + 3 < end; k += 6) {        // 2 edges in flight per subgroup
        int s0 = g_eidx[k], s1 = g_eidx[k + 3];
        float4 v0 = *(const float4*)(g_y2 + (size_t)s0 * 40 + q * 4);
        float4 v1 = *(const float4*)(g_y2 + (size_t)s1 * 40 + q * 4);
        acc.x += v0.x + v1.x; acc.y += v0.y + v1.y;
        acc.z += v0.z + v1.z; acc.w += v0.w + v1.w;
    }
    if (k < end) {
        int s = g_eidx[k];
        float4 v = *(const float4*)(g_y2 + (size_t)s * 40 + q * 4);
        acc.x += v.x; acc.y += v.y; acc.z += v.z; acc.w += v.w;
    }
    unsigned m = 0xFFFFFFFFu;
    float ax = acc.x + __shfl_sync(m, acc.x, lane + 10) + __shfl_sync(m, acc.x, lane + 20);
    float ay = acc.y + __shfl_sync(m, acc.y, lane + 10) + __shfl_sync(m, acc.y, lane + 20);
    float az = acc.z + __shfl_sync(m, acc.z, lane + 10) + __shfl_sync(m, acc.z, lane + 20);
    float aw = acc.w + __shfl_sync(m, acc.w, lane + 10) + __shfl_sync(m, acc.w, lane + 20);
    if (lane < 10) {
        float di = g_dinv[n];
        float4 b = ((const float4*)b2)[q];
        float4 r;
        r.x = fmaf(di, ax, b.x);
        r.y = fmaf(di, ay, b.y);
        r.z = fmaf(di, az, b.z);
        r.w = fmaf(di, aw, b.w);
        ((float4*)(out + (size_t)n * 40))[q] = r;
    }
}

extern "C" void kernel_launch(void* const* d_in, const int* in_sizes, int n_in,
                              void* d_out, int out_size) {
    const float* x    = (const float*)d_in[0];
    const int*   ei32 = (const int*)d_in[1];
    const float* W1   = (const float*)d_in[2];
    const float* b1   = (const float*)d_in[3];
    const float* W2   = (const float*)d_in[4];
    const float* b2   = (const float*)d_in[5];
    float*       out  = (float*)d_out;

    const int nn = in_sizes[0] / 128;     // 50000
    const int ne = in_sizes[1] / 2;       // 640000
    const int nb = (nn + 255) / 256;

    const int smem1 = (2 * 128 * 136 + 2 * 128 * 136) * 2;   // 139264 B
    const int smem2 = (2 * 128 * 136 + 2 * 128 * 56) * 2;    //  98304 B
    cudaFuncSetAttribute(k_gemm_tc<1>, cudaFuncAttributeMaxDynamicSharedMemorySize, smem1);
    cudaFuncSetAttribute(k_gemm_tc<2>, cudaFuncAttributeMaxDynamicSharedMemorySize, smem2);

    k_probe<<<1, 256>>>(ei32);
    k_zero_deg<<<nb, 256>>>(nn);
    k_count<<<(ne + 255) / 256, 256>>>(ei32, ne, nn);
    k_scan1<<<nb, 256>>>(nn);
    k_scan2<<<1, 256>>>(nb);
    k_scan3<<<nb, 256>>>(nn, ne);
    k_fill<<<(ne + 255) / 256, 256>>>(ei32, ne, nn);
    k_splitW<<<(128 * 128 + 128 * 40 + 255) / 256, 256>>>(W1, W2);

    int gblk = (nn + 127) / 128;
    k_gemm_tc<1><<<gblk, 256, smem1>>>(x, nn);
    k_gather1<<<(nn + 7) / 8, 256>>>(b1, nn);
    k_gemm_tc<2><<<gblk, 256, smem2>>>(nullptr, nn);
    k_gather2<<<(nn + 7) / 8, 256>>>(out, b2, nn);
}